// round 1
// baseline (speedup 1.0000x reference)
#include <cuda_runtime.h>
#include <cuda_bf16.h>

#define N_NODES 100000
#define E_EDGES 1600000
#define F_IN    256
#define HEADS   8
#define C1      8
#define F1      64      // HEADS*C1
#define NCLS    16
#define NEG     0.2f
#define NBLK_SCAN 98    // ceil(N/1024)

// ---------------- scratch (device globals: allocation-free) ----------------
__device__ float g_h1[N_NODES * F1];
__device__ float g_h1act[N_NODES * F1];
__device__ float g_al1s[N_NODES * HEADS];
__device__ float g_al1d[N_NODES * HEADS];
__device__ float g_h2[N_NODES * NCLS];
__device__ float g_al2s[N_NODES];
__device__ float g_al2d[N_NODES];
__device__ int   g_deg[N_NODES];
__device__ int   g_off[N_NODES];
__device__ int   g_cur[N_NODES];
__device__ int   g_esrc[E_EDGES];
__device__ int   g_bsums[256];
__device__ int   g_is64;

__device__ __forceinline__ float leakyf(float x) { return fmaxf(x, NEG * x); }

// ---------------- dtype detection for edge_index ----------------
__global__ void k_detect(const void* ei) {
    const unsigned long long* p = (const unsigned long long*)ei;
    int ok = 1;
    for (int i = 0; i < 256; i++)
        if (p[i] >= (unsigned long long)N_NODES) { ok = 0; break; }
    g_is64 = ok;
}

__device__ __forceinline__ int load_edge(const void* ei, long long idx, int is64) {
    if (is64) return (int)((const long long*)ei)[idx];
    return ((const int*)ei)[idx];
}

// ---------------- CSR build ----------------
__global__ void k_zero_deg() {
    int i = blockIdx.x * blockDim.x + threadIdx.x;
    if (i < N_NODES) g_deg[i] = 0;
}

__global__ void k_hist(const void* ei) {
    int e = blockIdx.x * blockDim.x + threadIdx.x;
    if (e >= E_EDGES) return;
    int is64 = g_is64;
    int dst = load_edge(ei, (long long)E_EDGES + e, is64);
    atomicAdd(&g_deg[dst], 1);
}

// exclusive scan over N elements, 1024 per block (256 threads x 4)
__global__ void k_scan1() {
    __shared__ int wsum[8];
    int b = blockIdx.x, t = threadIdx.x;
    int base = b * 1024 + t * 4;
    int v[4];
#pragma unroll
    for (int i = 0; i < 4; i++) v[i] = (base + i < N_NODES) ? g_deg[base + i] : 0;
    int s = v[0] + v[1] + v[2] + v[3];
    int lane = t & 31, w = t >> 5;
    int inc = s;
#pragma unroll
    for (int o = 1; o < 32; o <<= 1) {
        int u = __shfl_up_sync(0xffffffffu, inc, o);
        if (lane >= o) inc += u;
    }
    if (lane == 31) wsum[w] = inc;
    __syncthreads();
    if (t == 0) {
        int a = 0;
        for (int i = 0; i < 8; i++) { int x = wsum[i]; wsum[i] = a; a += x; }
        g_bsums[b] = a;
    }
    __syncthreads();
    int run = wsum[w] + (inc - s);  // exclusive prefix for this thread
#pragma unroll
    for (int i = 0; i < 4; i++) {
        if (base + i < N_NODES) g_off[base + i] = run;
        run += v[i];
    }
}

__global__ void k_scan2() {
    if (threadIdx.x == 0) {
        int a = 0;
        for (int i = 0; i < NBLK_SCAN; i++) { int x = g_bsums[i]; g_bsums[i] = a; a += x; }
    }
}

__global__ void k_scan3() {
    int i = blockIdx.x * blockDim.x + threadIdx.x;
    if (i < N_NODES) {
        int o = g_off[i] + g_bsums[i >> 10];
        g_off[i] = o;
        g_cur[i] = o;
    }
}

__global__ void k_scatter(const void* ei) {
    int e = blockIdx.x * blockDim.x + threadIdx.x;
    if (e >= E_EDGES) return;
    int is64 = g_is64;
    int src = load_edge(ei, e, is64);
    int dst = load_edge(ei, (long long)E_EDGES + e, is64);
    int pos = atomicAdd(&g_cur[dst], 1);
    g_esrc[pos] = src;
}

// ---------------- GEMM1: h1 = x @ W1   [N,256]@[256,64] ----------------
__global__ void k_gemm1(const float* __restrict__ x, const float* __restrict__ W1) {
    __shared__ float xs[64][68];  // node-major; pitch 68 keeps 16B alignment
    __shared__ float ws[64][64];  // k-major
    int tid = threadIdx.x;        // 256
    int tx = tid & 15;            // col group (4 cols)
    int ty = tid >> 4;            // node group (4 nodes)
    int nodeBase = blockIdx.x * 64;
    float acc[4][4];
#pragma unroll
    for (int i = 0; i < 4; i++)
#pragma unroll
        for (int j = 0; j < 4; j++) acc[i][j] = 0.f;

    for (int k0 = 0; k0 < F_IN; k0 += 64) {
#pragma unroll
        for (int r = 0; r < 4; r++) {
            int n = (tid >> 4) + r * 16;
            int gn = nodeBase + n;
            float4 v = make_float4(0.f, 0.f, 0.f, 0.f);
            if (gn < N_NODES)
                v = *(const float4*)&x[(long long)gn * F_IN + k0 + (tid & 15) * 4];
            *(float4*)&xs[n][(tid & 15) * 4] = v;
        }
#pragma unroll
        for (int r = 0; r < 4; r++) {
            int kk = (tid >> 4) + r * 16;
            float4 v = *(const float4*)&W1[(k0 + kk) * F1 + (tid & 15) * 4];
            *(float4*)&ws[kk][(tid & 15) * 4] = v;
        }
        __syncthreads();
#pragma unroll
        for (int k = 0; k < 64; k++) {
            float a0 = xs[ty * 4 + 0][k];
            float a1 = xs[ty * 4 + 1][k];
            float a2 = xs[ty * 4 + 2][k];
            float a3 = xs[ty * 4 + 3][k];
            float4 b = *(float4*)&ws[k][tx * 4];
            acc[0][0] += a0 * b.x; acc[0][1] += a0 * b.y; acc[0][2] += a0 * b.z; acc[0][3] += a0 * b.w;
            acc[1][0] += a1 * b.x; acc[1][1] += a1 * b.y; acc[1][2] += a1 * b.z; acc[1][3] += a1 * b.w;
            acc[2][0] += a2 * b.x; acc[2][1] += a2 * b.y; acc[2][2] += a2 * b.z; acc[2][3] += a2 * b.w;
            acc[3][0] += a3 * b.x; acc[3][1] += a3 * b.y; acc[3][2] += a3 * b.z; acc[3][3] += a3 * b.w;
        }
        __syncthreads();
    }
#pragma unroll
    for (int i = 0; i < 4; i++) {
        int gn = nodeBase + ty * 4 + i;
        if (gn < N_NODES) {
            float4 v = make_float4(acc[i][0], acc[i][1], acc[i][2], acc[i][3]);
            *(float4*)&g_h1[(long long)gn * F1 + tx * 4] = v;
        }
    }
}

// ---------------- per-(node,head) attention logits for layer 1 ----------------
__global__ void k_al1(const float* __restrict__ a1s, const float* __restrict__ a1d) {
    int gid = blockIdx.x * blockDim.x + threadIdx.x;
    if (gid >= N_NODES * HEADS) return;
    int node = gid >> 3, h = gid & 7;
    const float* hp = &g_h1[(long long)node * F1 + h * C1];
    float4 v0 = *(const float4*)&hp[0];
    float4 v1 = *(const float4*)&hp[4];
    const float* as = &a1s[h * C1];
    const float* ad = &a1d[h * C1];
    float ss = v0.x * as[0] + v0.y * as[1] + v0.z * as[2] + v0.w * as[3]
             + v1.x * as[4] + v1.y * as[5] + v1.z * as[6] + v1.w * as[7];
    float sd = v0.x * ad[0] + v0.y * ad[1] + v0.z * ad[2] + v0.w * ad[3]
             + v1.x * ad[4] + v1.y * ad[5] + v1.z * ad[6] + v1.w * ad[7];
    g_al1s[gid] = ss;
    g_al1d[gid] = sd;
}

// ---------------- gather attention layer 1 (8 threads per node) ----------------
__global__ void k_gather1(const float* __restrict__ b1) {
    int t = threadIdx.x;
    int h = t & 7;
    int node = blockIdx.x * 32 + (t >> 3);
    if (node >= N_NODES) return;

    float ald = g_al1d[node * HEADS + h];
    // self-loop init
    float e0 = leakyf(g_al1s[node * HEADS + h] + ald);
    float M = e0, S = 1.f;
    const float* selfp = &g_h1[(long long)node * F1 + h * C1];
    float4 accA = *(const float4*)&selfp[0];
    float4 accB = *(const float4*)&selfp[4];

    int beg = g_off[node], end = g_cur[node];
    for (int j = beg; j < end; j++) {
        int s = g_esrc[j];
        float e = leakyf(g_al1s[s * HEADS + h] + ald);
        const float* hp = &g_h1[(long long)s * F1 + h * C1];
        float4 hA = *(const float4*)&hp[0];
        float4 hB = *(const float4*)&hp[4];
        float d = e - M;
        if (d > 0.f) {
            float sc = __expf(-d);
            S = S * sc + 1.f;
            accA.x = accA.x * sc + hA.x; accA.y = accA.y * sc + hA.y;
            accA.z = accA.z * sc + hA.z; accA.w = accA.w * sc + hA.w;
            accB.x = accB.x * sc + hB.x; accB.y = accB.y * sc + hB.y;
            accB.z = accB.z * sc + hB.z; accB.w = accB.w * sc + hB.w;
            M = e;
        } else {
            float p = __expf(d);
            S += p;
            accA.x += p * hA.x; accA.y += p * hA.y; accA.z += p * hA.z; accA.w += p * hA.w;
            accB.x += p * hB.x; accB.y += p * hB.y; accB.z += p * hB.z; accB.w += p * hB.w;
        }
    }
    float inv = 1.f / S;
    float out[8] = { accA.x * inv, accA.y * inv, accA.z * inv, accA.w * inv,
                     accB.x * inv, accB.y * inv, accB.z * inv, accB.w * inv };
    float4 o0, o1;
    float* op = (float*)&o0;
#pragma unroll
    for (int c = 0; c < 8; c++) {
        float v = out[c] + b1[h * C1 + c];
        float act = (v > 0.f) ? v : (__expf(v) - 1.f);  // ELU
        ((float*)&o0)[0]; // no-op to keep compiler honest
        if (c < 4) ((float*)&o0)[c] = act; else ((float*)&o1)[c - 4] = act;
    }
    (void)op;
    float* dstp = &g_h1act[(long long)node * F1 + h * C1];
    *(float4*)&dstp[0] = o0;
    *(float4*)&dstp[4] = o1;
}

// ---------------- GEMM2: h2 = h1act @ W2  [N,64]@[64,16] + logits ----------------
__global__ void k_gemm2(const float* __restrict__ W2,
                        const float* __restrict__ a2s, const float* __restrict__ a2d) {
    __shared__ float ws[64][16];
    int tid = threadIdx.x;
    // cooperative load of W2 (1024 floats) by 256 threads
#pragma unroll
    for (int r = 0; r < 4; r++) {
        int idx = tid + r * 256;
        ws[idx >> 4][idx & 15] = W2[idx];
    }
    __syncthreads();
    int node = blockIdx.x * blockDim.x + tid;
    if (node >= N_NODES) return;

    float4 xr[16];
    const float4* xp = (const float4*)&g_h1act[(long long)node * F1];
#pragma unroll
    for (int i = 0; i < 16; i++) xr[i] = xp[i];

    float acc[16];
#pragma unroll
    for (int c = 0; c < 16; c++) acc[c] = 0.f;
#pragma unroll
    for (int i = 0; i < 16; i++) {
        float xv[4] = { xr[i].x, xr[i].y, xr[i].z, xr[i].w };
#pragma unroll
        for (int q = 0; q < 4; q++) {
            int k = i * 4 + q;
#pragma unroll
            for (int c = 0; c < 16; c++) acc[c] += xv[q] * ws[k][c];
        }
    }
    float ss = 0.f, sd = 0.f;
#pragma unroll
    for (int c = 0; c < 16; c++) { ss += acc[c] * a2s[c]; sd += acc[c] * a2d[c]; }
    float* hp = &g_h2[(long long)node * NCLS];
#pragma unroll
    for (int c = 0; c < 16; c += 4)
        *(float4*)&hp[c] = make_float4(acc[c], acc[c + 1], acc[c + 2], acc[c + 3]);
    g_al2s[node] = ss;
    g_al2d[node] = sd;
}

// ---------------- gather layer 2 (4 threads/node) + log_softmax ----------------
__global__ void k_gather2(const float* __restrict__ b2, float* __restrict__ out) {
    int t = threadIdx.x;
    int q = t & 3;                       // channel group: 4q..4q+3
    int node = blockIdx.x * 64 + (t >> 2);
    if (node >= N_NODES) return;

    float ald = g_al2d[node];
    float e0 = leakyf(g_al2s[node] + ald);
    float M = e0, S = 1.f;
    float4 acc = *(const float4*)&g_h2[(long long)node * NCLS + q * 4];

    int beg = g_off[node], end = g_cur[node];
    for (int j = beg; j < end; j++) {
        int s = g_esrc[j];
        float e = leakyf(g_al2s[s] + ald);
        float4 hv = *(const float4*)&g_h2[(long long)s * NCLS + q * 4];
        float d = e - M;
        if (d > 0.f) {
            float sc = __expf(-d);
            S = S * sc + 1.f;
            acc.x = acc.x * sc + hv.x; acc.y = acc.y * sc + hv.y;
            acc.z = acc.z * sc + hv.z; acc.w = acc.w * sc + hv.w;
            M = e;
        } else {
            float p = __expf(d);
            S += p;
            acc.x += p * hv.x; acc.y += p * hv.y; acc.z += p * hv.z; acc.w += p * hv.w;
        }
    }
    float inv = 1.f / S;
    float v[4];
#pragma unroll
    for (int i = 0; i < 4; i++)
        v[i] = ((float*)&acc)[i] * inv + b2[q * 4 + i];

    // log_softmax across the 16 values held by 4 threads
    float m4 = fmaxf(fmaxf(v[0], v[1]), fmaxf(v[2], v[3]));
    m4 = fmaxf(m4, __shfl_xor_sync(0xffffffffu, m4, 1, 4));
    m4 = fmaxf(m4, __shfl_xor_sync(0xffffffffu, m4, 2, 4));
    float se = __expf(v[0] - m4) + __expf(v[1] - m4) + __expf(v[2] - m4) + __expf(v[3] - m4);
    se += __shfl_xor_sync(0xffffffffu, se, 1, 4);
    se += __shfl_xor_sync(0xffffffffu, se, 2, 4);
    float lse = m4 + __logf(se);
    float* op = &out[(long long)node * NCLS + q * 4];
    op[0] = v[0] - lse; op[1] = v[1] - lse; op[2] = v[2] - lse; op[3] = v[3] - lse;
}

// ---------------- launch ----------------
extern "C" void kernel_launch(void* const* d_in, const int* in_sizes, int n_in,
                              void* d_out, int out_size) {
    const float* x   = (const float*)d_in[0];
    const void*  ei  = d_in[1];
    const float* W1  = (const float*)d_in[2];
    const float* a1s = (const float*)d_in[3];
    const float* a1d = (const float*)d_in[4];
    const float* b1  = (const float*)d_in[5];
    const float* W2  = (const float*)d_in[6];
    const float* a2s = (const float*)d_in[7];
    const float* a2d = (const float*)d_in[8];
    const float* b2  = (const float*)d_in[9];
    float* outp = (float*)d_out;

    k_detect<<<1, 1>>>(ei);
    k_zero_deg<<<(N_NODES + 255) / 256, 256>>>();
    k_hist<<<(E_EDGES + 255) / 256, 256>>>(ei);
    k_scan1<<<NBLK_SCAN, 256>>>();
    k_scan2<<<1, 32>>>();
    k_scan3<<<(N_NODES + 255) / 256, 256>>>();
    k_scatter<<<(E_EDGES + 255) / 256, 256>>>(ei);

    k_gemm1<<<(N_NODES + 63) / 64, 256>>>(x, W1);
    k_al1<<<(N_NODES * HEADS + 255) / 256, 256>>>(a1s, a1d);
    k_gather1<<<(N_NODES + 31) / 32, 256>>>(b1);

    k_gemm2<<<(N_NODES + 255) / 256, 256>>>(W2, a2s, a2d);
    k_gather2<<<(N_NODES + 63) / 64, 256>>>(b2, outp);
}

// round 2
// speedup vs baseline: 1.0195x; 1.0195x over previous
#include <cuda_runtime.h>
#include <cuda_bf16.h>

#define N_NODES 100000
#define E_EDGES 1600000
#define F_IN    256
#define HEADS   8
#define C1      8
#define F1      64
#define NCLS    16
#define NEG     0.2f
#define NBLK_SCAN 98

// ---------------- scratch ----------------
__device__ float g_h1[N_NODES * F1];
__device__ float g_h1act[N_NODES * F1];
__device__ float g_al1s[N_NODES * HEADS];
__device__ float g_al1d[N_NODES * HEADS];
__device__ float g_h2[N_NODES * NCLS];
__device__ float g_al2s[N_NODES];
__device__ float g_al2d[N_NODES];
__device__ int   g_deg[N_NODES];
__device__ int   g_off[N_NODES];
__device__ int   g_cur[N_NODES];
__device__ int   g_esrc[E_EDGES];
__device__ int   g_bsums[256];
__device__ int   g_is64;

__device__ __forceinline__ float leakyf(float x) { return fmaxf(x, NEG * x); }

// ---- f32x2 helpers (Blackwell packed fp32 FMA) ----
__device__ __forceinline__ unsigned long long pk2(float a) {
    unsigned long long r; asm("mov.b64 %0, {%1, %1};" : "=l"(r) : "f"(a)); return r;
}
__device__ __forceinline__ unsigned long long pk(float a, float b) {
    unsigned long long r; asm("mov.b64 %0, {%1, %2};" : "=l"(r) : "f"(a), "f"(b)); return r;
}
__device__ __forceinline__ void fma2(unsigned long long& d, unsigned long long a, unsigned long long b) {
    asm("fma.rn.f32x2 %0, %1, %2, %0;" : "+l"(d) : "l"(a), "l"(b));
}
__device__ __forceinline__ float2 upk(unsigned long long v) {
    float2 f; asm("mov.b64 {%0, %1}, %2;" : "=f"(f.x), "=f"(f.y) : "l"(v)); return f;
}

__device__ __forceinline__ int load_edge(const void* ei, long long idx, int is64) {
    if (is64) return (int)((const long long*)ei)[idx];
    return ((const int*)ei)[idx];
}

// ---------------- init: zero deg + parallel dtype detect ----------------
__global__ void k_init(const void* ei) {
    int i = blockIdx.x * blockDim.x + threadIdx.x;
    if (i < N_NODES) g_deg[i] = 0;
    if (blockIdx.x == 0) {
        const unsigned long long* p = (const unsigned long long*)ei;
        int ok = (p[threadIdx.x] < (unsigned long long)N_NODES) ? 1 : 0;
        int all = __syncthreads_and(ok);
        if (threadIdx.x == 0) g_is64 = all;
    }
}

__global__ void k_hist(const void* ei) {
    int e = blockIdx.x * blockDim.x + threadIdx.x;
    if (e >= E_EDGES) return;
    int dst = load_edge(ei, (long long)E_EDGES + e, g_is64);
    atomicAdd(&g_deg[dst], 1);
}

__global__ void k_scan1() {
    __shared__ int wsum[8];
    int b = blockIdx.x, t = threadIdx.x;
    int base = b * 1024 + t * 4;
    int v[4];
#pragma unroll
    for (int i = 0; i < 4; i++) v[i] = (base + i < N_NODES) ? g_deg[base + i] : 0;
    int s = v[0] + v[1] + v[2] + v[3];
    int lane = t & 31, w = t >> 5;
    int inc = s;
#pragma unroll
    for (int o = 1; o < 32; o <<= 1) {
        int u = __shfl_up_sync(0xffffffffu, inc, o);
        if (lane >= o) inc += u;
    }
    if (lane == 31) wsum[w] = inc;
    __syncthreads();
    if (t == 0) {
        int a = 0;
        for (int i = 0; i < 8; i++) { int x = wsum[i]; wsum[i] = a; a += x; }
        g_bsums[b] = a;
    }
    __syncthreads();
    int run = wsum[w] + (inc - s);
#pragma unroll
    for (int i = 0; i < 4; i++) {
        if (base + i < N_NODES) g_off[base + i] = run;
        run += v[i];
    }
}

__global__ void k_scan2() {
    if (threadIdx.x == 0) {
        int a = 0;
        for (int i = 0; i < NBLK_SCAN; i++) { int x = g_bsums[i]; g_bsums[i] = a; a += x; }
    }
}

__global__ void k_scan3() {
    int i = blockIdx.x * blockDim.x + threadIdx.x;
    if (i < N_NODES) {
        int o = g_off[i] + g_bsums[i >> 10];
        g_off[i] = o;
        g_cur[i] = o;
    }
}

__global__ void k_scatter(const void* ei) {
    int e = blockIdx.x * blockDim.x + threadIdx.x;
    if (e >= E_EDGES) return;
    int is64 = g_is64;
    int src = load_edge(ei, e, is64);
    int dst = load_edge(ei, (long long)E_EDGES + e, is64);
    int pos = atomicAdd(&g_cur[dst], 1);
    g_esrc[pos] = src;
}

// ---------------- GEMM1 (f32x2) + fused attention-logit epilogue ----------------
// block: 128 nodes x 64 cols, 256 threads, thread = 8 nodes x 4 cols
__global__ __launch_bounds__(256) void k_gemm1(const float* __restrict__ x,
                                               const float* __restrict__ W1,
                                               const float* __restrict__ a1s,
                                               const float* __restrict__ a1d) {
    __shared__ float xs[128][68];
    __shared__ float ws[64][64];
    int tid = threadIdx.x;
    int tx = tid & 15;            // col group (4 cols)
    int ty = tid >> 4;            // node group (8 nodes)
    int nodeBase = blockIdx.x * 128;

    unsigned long long acc[8][2];
#pragma unroll
    for (int i = 0; i < 8; i++) { acc[i][0] = 0ull; acc[i][1] = 0ull; }

    for (int k0 = 0; k0 < F_IN; k0 += 64) {
#pragma unroll
        for (int r = 0; r < 8; r++) {
            int n = ty + r * 16;
            int gn = nodeBase + n;
            float4 v = make_float4(0.f, 0.f, 0.f, 0.f);
            if (gn < N_NODES)
                v = *(const float4*)&x[(long long)gn * F_IN + k0 + tx * 4];
            *(float4*)&xs[n][tx * 4] = v;
        }
#pragma unroll
        for (int r = 0; r < 4; r++) {
            int kk = ty + r * 16;
            float4 v = *(const float4*)&W1[(k0 + kk) * F1 + tx * 4];
            *(float4*)&ws[kk][tx * 4] = v;
        }
        __syncthreads();
#pragma unroll 4
        for (int k = 0; k < 64; k++) {
            float4 b = *(float4*)&ws[k][tx * 4];
            unsigned long long b01 = pk(b.x, b.y);
            unsigned long long b23 = pk(b.z, b.w);
#pragma unroll
            for (int i = 0; i < 8; i++) {
                unsigned long long aa = pk2(xs[ty * 8 + i][k]);
                fma2(acc[i][0], aa, b01);
                fma2(acc[i][1], aa, b23);
            }
        }
        __syncthreads();
    }

    int head = tx >> 1;
    int sub = (tx & 1) * 4;
    float as0 = a1s[head * C1 + sub + 0], as1 = a1s[head * C1 + sub + 1];
    float as2 = a1s[head * C1 + sub + 2], as3 = a1s[head * C1 + sub + 3];
    float ad0 = a1d[head * C1 + sub + 0], ad1 = a1d[head * C1 + sub + 1];
    float ad2 = a1d[head * C1 + sub + 2], ad3 = a1d[head * C1 + sub + 3];

#pragma unroll
    for (int i = 0; i < 8; i++) {
        int gn = nodeBase + ty * 8 + i;
        float2 v01 = upk(acc[i][0]);
        float2 v23 = upk(acc[i][1]);
        float4 v = make_float4(v01.x, v01.y, v23.x, v23.y);
        if (gn < N_NODES)
            *(float4*)&g_h1[(long long)gn * F1 + tx * 4] = v;
        float ss = v.x * as0 + v.y * as1 + v.z * as2 + v.w * as3;
        float sd = v.x * ad0 + v.y * ad1 + v.z * ad2 + v.w * ad3;
        ss += __shfl_xor_sync(0xffffffffu, ss, 1);
        sd += __shfl_xor_sync(0xffffffffu, sd, 1);
        if ((tx & 1) == 0 && gn < N_NODES) {
            g_al1s[gn * HEADS + head] = ss;
            g_al1d[gn * HEADS + head] = sd;
        }
    }
}

// ---------------- gather layer 1: no-max softmax, f32x2 ----------------
__global__ __launch_bounds__(256) void k_gather1(const float* __restrict__ b1) {
    int t = threadIdx.x;
    int h = t & 7;
    int node = blockIdx.x * 32 + (t >> 3);
    if (node >= N_NODES) return;

    float ald = g_al1d[node * HEADS + h];
    // self-loop
    float p0 = __expf(leakyf(g_al1s[node * HEADS + h] + ald));
    float S = p0;
    unsigned long long pp = pk2(p0);
    const float* selfp = &g_h1[(long long)node * F1 + h * C1];
    ulonglong2 sv0 = *(const ulonglong2*)&selfp[0];
    ulonglong2 sv1 = *(const ulonglong2*)&selfp[4];
    unsigned long long a0 = 0ull, a1 = 0ull, a2 = 0ull, a3 = 0ull;
    fma2(a0, pp, sv0.x); fma2(a1, pp, sv0.y);
    fma2(a2, pp, sv1.x); fma2(a3, pp, sv1.y);

    int beg = g_off[node], end = g_cur[node];
    for (int j = beg; j < end; j++) {
        int s = g_esrc[j];
        float p = __expf(leakyf(g_al1s[s * HEADS + h] + ald));
        const float* hp = &g_h1[(long long)s * F1 + h * C1];
        ulonglong2 hv0 = *(const ulonglong2*)&hp[0];
        ulonglong2 hv1 = *(const ulonglong2*)&hp[4];
        S += p;
        unsigned long long pe = pk2(p);
        fma2(a0, pe, hv0.x); fma2(a1, pe, hv0.y);
        fma2(a2, pe, hv1.x); fma2(a3, pe, hv1.y);
    }
    float inv = 1.f / S;
    float2 f0 = upk(a0), f1 = upk(a1), f2 = upk(a2), f3 = upk(a3);
    float out[8] = { f0.x, f0.y, f1.x, f1.y, f2.x, f2.y, f3.x, f3.y };
    float res[8];
#pragma unroll
    for (int c = 0; c < 8; c++) {
        float v = out[c] * inv + b1[h * C1 + c];
        res[c] = (v > 0.f) ? v : (__expf(v) - 1.f);  // ELU
    }
    float* dstp = &g_h1act[(long long)node * F1 + h * C1];
    *(float4*)&dstp[0] = make_float4(res[0], res[1], res[2], res[3]);
    *(float4*)&dstp[4] = make_float4(res[4], res[5], res[6], res[7]);
}

// ---------------- GEMM2 + fused layer-2 logits ----------------
__global__ __launch_bounds__(256) void k_gemm2(const float* __restrict__ W2,
                                               const float* __restrict__ a2s,
                                               const float* __restrict__ a2d) {
    __shared__ float ws[64][16];
    int tid = threadIdx.x;
#pragma unroll
    for (int r = 0; r < 4; r++) {
        int idx = tid + r * 256;
        ws[idx >> 4][idx & 15] = W2[idx];
    }
    __syncthreads();
    int node = blockIdx.x * blockDim.x + tid;
    if (node >= N_NODES) return;

    const float4* xp = (const float4*)&g_h1act[(long long)node * F1];
    float acc[16];
#pragma unroll
    for (int c = 0; c < 16; c++) acc[c] = 0.f;
#pragma unroll
    for (int i = 0; i < 16; i++) {
        float4 xv = xp[i];
        float v[4] = { xv.x, xv.y, xv.z, xv.w };
#pragma unroll
        for (int q = 0; q < 4; q++) {
            int k = i * 4 + q;
#pragma unroll
            for (int c = 0; c < 16; c++) acc[c] += v[q] * ws[k][c];
        }
    }
    float ss = 0.f, sd = 0.f;
#pragma unroll
    for (int c = 0; c < 16; c++) { ss += acc[c] * a2s[c]; sd += acc[c] * a2d[c]; }
    float* hp = &g_h2[(long long)node * NCLS];
#pragma unroll
    for (int c = 0; c < 16; c += 4)
        *(float4*)&hp[c] = make_float4(acc[c], acc[c + 1], acc[c + 2], acc[c + 3]);
    g_al2s[node] = ss;
    g_al2d[node] = sd;
}

// ---------------- gather layer 2 + log_softmax ----------------
__global__ __launch_bounds__(256) void k_gather2(const float* __restrict__ b2,
                                                 float* __restrict__ out) {
    int t = threadIdx.x;
    int q = t & 3;
    int node = blockIdx.x * 64 + (t >> 2);
    if (node >= N_NODES) return;

    float ald = g_al2d[node];
    float p0 = __expf(leakyf(g_al2s[node] + ald));
    float S = p0;
    ulonglong2 sv = *(const ulonglong2*)&g_h2[(long long)node * NCLS + q * 4];
    unsigned long long a0 = 0ull, a1 = 0ull;
    unsigned long long pp = pk2(p0);
    fma2(a0, pp, sv.x); fma2(a1, pp, sv.y);

    int beg = g_off[node], end = g_cur[node];
    for (int j = beg; j < end; j++) {
        int s = g_esrc[j];
        float p = __expf(leakyf(g_al2s[s] + ald));
        ulonglong2 hv = *(const ulonglong2*)&g_h2[(long long)s * NCLS + q * 4];
        S += p;
        unsigned long long pe = pk2(p);
        fma2(a0, pe, hv.x); fma2(a1, pe, hv.y);
    }
    float inv = 1.f / S;
    float2 f0 = upk(a0), f1 = upk(a1);
    float v[4];
    v[0] = f0.x * inv + b2[q * 4 + 0];
    v[1] = f0.y * inv + b2[q * 4 + 1];
    v[2] = f1.x * inv + b2[q * 4 + 2];
    v[3] = f1.y * inv + b2[q * 4 + 3];

    float m4 = fmaxf(fmaxf(v[0], v[1]), fmaxf(v[2], v[3]));
    m4 = fmaxf(m4, __shfl_xor_sync(0xffffffffu, m4, 1, 4));
    m4 = fmaxf(m4, __shfl_xor_sync(0xffffffffu, m4, 2, 4));
    float se = __expf(v[0] - m4) + __expf(v[1] - m4) + __expf(v[2] - m4) + __expf(v[3] - m4);
    se += __shfl_xor_sync(0xffffffffu, se, 1, 4);
    se += __shfl_xor_sync(0xffffffffu, se, 2, 4);
    float lse = m4 + __logf(se);
    float* op = &out[(long long)node * NCLS + q * 4];
    op[0] = v[0] - lse; op[1] = v[1] - lse; op[2] = v[2] - lse; op[3] = v[3] - lse;
}

// ---------------- launch ----------------
extern "C" void kernel_launch(void* const* d_in, const int* in_sizes, int n_in,
                              void* d_out, int out_size) {
    const float* x   = (const float*)d_in[0];
    const void*  ei  = d_in[1];
    const float* W1  = (const float*)d_in[2];
    const float* a1s = (const float*)d_in[3];
    const float* a1d = (const float*)d_in[4];
    const float* b1  = (const float*)d_in[5];
    const float* W2  = (const float*)d_in[6];
    const float* a2s = (const float*)d_in[7];
    const float* a2d = (const float*)d_in[8];
    const float* b2  = (const float*)d_in[9];
    float* outp = (float*)d_out;

    k_init<<<(N_NODES + 255) / 256, 256>>>(ei);
    k_hist<<<(E_EDGES + 255) / 256, 256>>>(ei);
    k_scan1<<<NBLK_SCAN, 256>>>();
    k_scan2<<<1, 32>>>();
    k_scan3<<<(N_NODES + 255) / 256, 256>>>();
    k_scatter<<<(E_EDGES + 255) / 256, 256>>>(ei);

    k_gemm1<<<(N_NODES + 127) / 128, 256>>>(x, W1, a1s, a1d);
    k_gather1<<<(N_NODES + 31) / 32, 256>>>(b1);

    k_gemm2<<<(N_NODES + 255) / 256, 256>>>(W2, a2s, a2d);
    k_gather2<<<(N_NODES + 63) / 64, 256>>>(b2, outp);
}